// round 15
// baseline (speedup 1.0000x reference)
#include <cuda_runtime.h>
#include <cstdint>

#define S_LEN 2048
#define D_DIM 2048
#define NH 32
#define NB 8
#define HB 256    // NH*NB
#define NBIG 2816 // 768 qkv + 2048 gate
#define K4 (D_DIM / 4)   // 512 int8x4 groups along K

// -------- scratch (no allocations allowed) --------
__device__ float g_pq[NH * S_LEN * NB];
__device__ float g_pk[NH * S_LEN * NB];
__device__ float g_pv[NH * S_LEN * NB];
__device__ float g_sumk[NH * S_LEN];
__device__ float g_op[S_LEN * HB];
__device__ float g_bias[D_DIM];

__device__ int g_amax_bits[2];             // [0]=hs, [1]=weights
__device__ int g_A1[K4 * S_LEN];           // packed hs hi  [k4][m]
__device__ int g_A2[K4 * S_LEN];           // packed hs lo
__device__ int g_B1[K4 * NBIG];            // packed weights hi [k4][n]
__device__ int g_B2[K4 * NBIG];            // packed weights lo

__device__ __forceinline__ float fsigmoid(float x) {
    return 1.0f / (1.0f + __expf(-x));
}
__device__ __forceinline__ uint32_t smem_u32(const void* p) {
    uint32_t a;
    asm("{ .reg .u64 t; cvta.to.shared.u64 t, %1; cvt.u32.u64 %0, t; }" : "=r"(a) : "l"(p));
    return a;
}
__device__ __forceinline__ void cp16(uint32_t dst, const void* src) {
    asm volatile("cp.async.cg.shared.global [%0], [%1], 16;" :: "r"(dst), "l"(src));
}
__device__ __forceinline__ void cp_commit() {
    asm volatile("cp.async.commit_group;" ::: "memory");
}
template <int N> __device__ __forceinline__ void cp_wait() {
    asm volatile("cp.async.wait_group %0;" :: "n"(N) : "memory");
}
__device__ __forceinline__ void fma2(float2& d, float2 a, float2 b) {
    asm("fma.rn.f32x2 %0, %1, %2, %0;"
        : "+l"(reinterpret_cast<unsigned long long&>(d))
        : "l"(reinterpret_cast<unsigned long long&>(a)),
          "l"(reinterpret_cast<unsigned long long&>(b)));
}
__device__ __forceinline__ float2 dup2(float a) {
    float2 r;
    asm("mov.b64 %0, {%1, %1};"
        : "=l"(reinterpret_cast<unsigned long long&>(r)) : "f"(a));
    return r;
}

// ---------------- amax ----------------
__global__ void init_amax() {
    if (threadIdx.x < 2) g_amax_bits[threadIdx.x] = 0;
}
__global__ void amax_kernel(const float* __restrict__ x, int n, int slot) {
    float m = 0.f;
    for (int i = blockIdx.x * blockDim.x + threadIdx.x; i < n; i += gridDim.x * blockDim.x)
        m = fmaxf(m, fabsf(x[i]));
#pragma unroll
    for (int o = 16; o > 0; o >>= 1)
        m = fmaxf(m, __shfl_xor_sync(0xffffffffu, m, o));
    if ((threadIdx.x & 31) == 0)
        atomicMax(&g_amax_bits[slot], __float_as_int(m));
}

// ---------------- int8 2-term packing ----------------
__device__ __forceinline__ int q8(float v, float inv_s) {
    float q = rintf(v * inv_s);
    q = fmaxf(-127.f, fminf(127.f, q));
    return (int)q;
}

// hs [M][K] -> g_A1/g_A2 [k4][M]
__global__ void pack_act(const float* __restrict__ hs) {
    __shared__ float t[32][33];
    int m0 = blockIdx.x * 32, k0 = blockIdx.y * 32;
    int tx = threadIdx.x, ty = threadIdx.y;
    float s1 = __int_as_float(g_amax_bits[0]) / 127.f;
    float s2 = s1 / 254.f;
    float i1 = 1.f / s1, i2 = 1.f / s2;
#pragma unroll
    for (int i = 0; i < 4; ++i)
        t[ty + 8 * i][tx] = hs[(size_t)(m0 + ty + 8 * i) * D_DIM + k0 + tx];
    __syncthreads();
    int w1 = 0, w2 = 0;
#pragma unroll
    for (int j = 0; j < 4; ++j) {
        float v = t[tx][4 * ty + j];
        int q1 = q8(v, i1);
        int q2 = q8(v - (float)q1 * s1, i2);
        w1 |= (q1 & 0xFF) << (8 * j);
        w2 |= (q2 & 0xFF) << (8 * j);
    }
    size_t o = (size_t)(k0 / 4 + ty) * S_LEN + m0 + tx;
    g_A1[o] = w1;
    g_A2[o] = w2;
}

// W [K][Nsrc] -> g_B1/g_B2 [k4][NBIG] at column offset ncol0
__global__ void pack_w(const float* __restrict__ W, int Nsrc, int ncol0) {
    __shared__ float t[32][33];
    int n0 = blockIdx.x * 32, k0 = blockIdx.y * 32;
    int tx = threadIdx.x, ty = threadIdx.y;
    float s1 = __int_as_float(g_amax_bits[1]) / 127.f;
    float s2 = s1 / 254.f;
    float i1 = 1.f / s1, i2 = 1.f / s2;
#pragma unroll
    for (int i = 0; i < 4; ++i)
        t[ty + 8 * i][tx] = W[(size_t)(k0 + ty + 8 * i) * Nsrc + n0 + tx];
    __syncthreads();
    int w1 = 0, w2 = 0;
#pragma unroll
    for (int j = 0; j < 4; ++j) {
        float v = t[4 * ty + j][tx];
        int q1 = q8(v, i1);
        int q2 = q8(v - (float)q1 * s1, i2);
        w1 |= (q1 & 0xFF) << (8 * j);
        w2 |= (q2 & 0xFF) << (8 * j);
    }
    size_t o = (size_t)(k0 / 4 + ty) * NBIG + ncol0 + n0 + tx;
    g_B1[o] = w1;
    g_B2[o] = w2;
}

// ---------------- fused qkv+gate int8 GEMM ----------------
// C[128,128] per CTA. K extended 3x: p0 A1*B1 (scale S0), p1 A2*B1, p2 A1*B2
// (both S0/254, shared int accumulator). 32 k per chunk (8 k4-rows).
#define ICH 8                       // k4 rows per chunk
#define ITILE (ICH * 128)           // ints per tile
__global__ void __launch_bounds__(256, 1) fused_int8(float* __restrict__ out) {
    __shared__ int As[2][ITILE];
    __shared__ int Bs[2][ITILE];
    const int tid = threadIdx.x;
    const int bcol = blockIdx.x * 128;
    const int brow = blockIdx.y * 128;

    const int lrow = tid >> 5, lc4 = (tid & 31) * 4;
    const int m0 = (tid >> 4) * 8, n0 = (tid & 15) * 8;

    int iacc[8][8];
    float facc[8][8];
#pragma unroll
    for (int a = 0; a < 8; ++a)
#pragma unroll
        for (int b = 0; b < 8; ++b) { iacc[a][b] = 0; facc[a][b] = 0.f; }

    const int NCH = 3 * (K4 / ICH);   // 192

    // prologue chunk 0
    cp16(smem_u32(&As[0][lrow * 128 + lc4]), g_A1 + (size_t)lrow * S_LEN + brow + lc4);
    cp16(smem_u32(&Bs[0][lrow * 128 + lc4]), g_B1 + (size_t)lrow * NBIG + bcol + lc4);
    cp_commit();

#pragma unroll 1
    for (int c = 0; c < NCH; ++c) {
        const int cn = c + 1;
        if (cn < NCH) {
            const int seg = cn >> 6;
            const int k4off = (cn & 63) * ICH;
            const int* Ag = (seg == 1) ? g_A2 : g_A1;
            const int* Bg = (seg == 2) ? g_B2 : g_B1;
            cp16(smem_u32(&As[cn & 1][lrow * 128 + lc4]),
                 Ag + (size_t)(k4off + lrow) * S_LEN + brow + lc4);
            cp16(smem_u32(&Bs[cn & 1][lrow * 128 + lc4]),
                 Bg + (size_t)(k4off + lrow) * NBIG + bcol + lc4);
        }
        cp_commit();
        cp_wait<1>();
        __syncthreads();

        const int* as = As[c & 1];
        const int* bs = Bs[c & 1];
#pragma unroll
        for (int k4 = 0; k4 < ICH; ++k4) {
            int4 a0 = *(const int4*)&as[k4 * 128 + m0];
            int4 a1 = *(const int4*)&as[k4 * 128 + m0 + 4];
            int4 b0 = *(const int4*)&bs[k4 * 128 + n0];
            int4 b1 = *(const int4*)&bs[k4 * 128 + n0 + 4];
            int a[8] = {a0.x, a0.y, a0.z, a0.w, a1.x, a1.y, a1.z, a1.w};
            int b[8] = {b0.x, b0.y, b0.z, b0.w, b1.x, b1.y, b1.z, b1.w};
#pragma unroll
            for (int mi = 0; mi < 8; ++mi)
#pragma unroll
                for (int ni = 0; ni < 8; ++ni)
                    iacc[mi][ni] = __dp4a(a[mi], b[ni], iacc[mi][ni]);
        }
        __syncthreads();

        if (c == 63) {  // end of hi*hi pass: fold; passes 1-2 share one scale
#pragma unroll
            for (int mi = 0; mi < 8; ++mi)
#pragma unroll
                for (int ni = 0; ni < 8; ++ni) {
                    facc[mi][ni] = (float)iacc[mi][ni];
                    iacc[mi][ni] = 0;
                }
        }
    }

    const float s1a = __int_as_float(g_amax_bits[0]) / 127.f;
    const float s1b = __int_as_float(g_amax_bits[1]) / 127.f;
    const float S0 = s1a * s1b;
    const float Slo = S0 * (1.f / 254.f);

    if (bcol < 768) {
        const int which = bcol >> 8;
        float* dst = (which == 0) ? g_pq : (which == 1) ? g_pk : g_pv;
        const float scl = (which == 0) ? 2.0f : 1.0f;
#pragma unroll
        for (int mi = 0; mi < 8; ++mi) {
            int s = brow + m0 + mi;
#pragma unroll
            for (int ni = 0; ni < 8; ni += 2) {
                int cg = bcol + n0 + ni;
                int rem = cg & 255;              // FIX: local column within matrix
                int h = rem >> 3, d = rem & 7;
                float p0 = S0 * facc[mi][ni]     + Slo * (float)iacc[mi][ni];
                float p1 = S0 * facc[mi][ni + 1] + Slo * (float)iacc[mi][ni + 1];
                *(float2*)&dst[((size_t)h * S_LEN + s) * NB + d] =
                    make_float2(scl * fsigmoid(p0), scl * fsigmoid(p1));
            }
        }
    } else {
        const int col0 = bcol - 768;
#pragma unroll
        for (int mi = 0; mi < 8; ++mi) {
            int r = brow + m0 + mi;
            size_t base = (size_t)r * D_DIM + col0 + n0;
            float v[8];
#pragma unroll
            for (int ni = 0; ni < 8; ++ni)
                v[ni] = S0 * facc[mi][ni] + Slo * (float)iacc[mi][ni];
            *(float4*)&out[base]     = make_float4(v[0], v[1], v[2], v[3]);
            *(float4*)&out[base + 4] = make_float4(v[4], v[5], v[6], v[7]);
        }
    }
}

// ---------------- f32 GEMM core (PROVEN R12) for final ----------------
#define GBK 16
#define AROW 20
#define ASZ (128 * AROW)
#define BSZ (GBK * 128)

__device__ __forceinline__ void g_load_chunk(
    const float* __restrict__ A, const float* __restrict__ B,
    int K, int Nst, int arow0, int bcol, int k0,
    float* as, float* bs, int tid)
{
#pragma unroll
    for (int i = 0; i < 2; ++i) {
        int idx = tid + i * 256;
        int r = idx >> 2, q = idx & 3;
        cp16(smem_u32(as + r * AROW + q * 4),
             A + (size_t)(arow0 + r) * K + k0 + q * 4);
    }
#pragma unroll
    for (int i = 0; i < 2; ++i) {
        int idx = tid + i * 256;
        int kr = idx >> 5, nq = idx & 31;
        cp16(smem_u32(bs + kr * 128 + nq * 4),
             B + (size_t)(k0 + kr) * Nst + bcol + nq * 4);
    }
}
__device__ __forceinline__ void g_compute_chunk(
    const float* __restrict__ as, const float* __restrict__ bs,
    int m0, int n0, float2 (&acc)[8][4])
{
#pragma unroll
    for (int k = 0; k < GBK; ++k) {
        float a[8];
#pragma unroll
        for (int mi = 0; mi < 8; ++mi) a[mi] = as[(m0 + mi) * AROW + k];
        float4 b0 = *(const float4*)&bs[k * 128 + n0];
        float4 b1 = *(const float4*)&bs[k * 128 + n0 + 4];
        float2 b2[4] = {{b0.x, b0.y}, {b0.z, b0.w}, {b1.x, b1.y}, {b1.z, b1.w}};
#pragma unroll
        for (int mi = 0; mi < 8; ++mi) {
            float2 am = dup2(a[mi]);
#pragma unroll
            for (int n2 = 0; n2 < 4; ++n2) fma2(acc[mi][n2], am, b2[n2]);
        }
    }
}

__global__ void __launch_bounds__(256) final_gemm(
    const float* __restrict__ Wo, float* __restrict__ out)
{
    __shared__ __align__(16) float As[2][ASZ];
    __shared__ __align__(16) float Bs[2][BSZ];
    const int tid = threadIdx.x;
    const int brow = blockIdx.y * 128;
    const int bcol = blockIdx.x * 128;

    float2 acc[8][4];
#pragma unroll
    for (int mi = 0; mi < 8; ++mi)
#pragma unroll
        for (int n2 = 0; n2 < 4; ++n2) acc[mi][n2] = make_float2(0.f, 0.f);

    const int m0 = (tid >> 4) * 8, n0 = (tid & 15) * 8;
    const int nch = HB / GBK;

    g_load_chunk(g_op, Wo, HB, D_DIM, brow, bcol, 0, As[0], Bs[0], tid);
    cp_commit();
    for (int c = 0; c < nch; ++c) {
        if (c + 1 < nch)
            g_load_chunk(g_op, Wo, HB, D_DIM, brow, bcol, (c + 1) * GBK,
                         As[(c + 1) & 1], Bs[(c + 1) & 1], tid);
        cp_commit();
        cp_wait<1>();
        __syncthreads();
        g_compute_chunk(As[c & 1], Bs[c & 1], m0, n0, acc);
        __syncthreads();
    }

#pragma unroll
    for (int mi = 0; mi < 8; ++mi) {
        int r = brow + m0 + mi;
        int c0 = bcol + n0;
        size_t base = (size_t)r * D_DIM + c0;
#pragma unroll
        for (int n2 = 0; n2 < 4; ++n2) {
            float2 b = *(float2*)&g_bias[c0 + 2 * n2];
            float2 g = *(float2*)&out[base + 2 * n2];
            float2 v;
            v.x = (acc[mi][n2].x + b.x) * fsigmoid(g.x);
            v.y = (acc[mi][n2].y + b.y) * fsigmoid(g.y);
            *(float2*)&out[base + 2 * n2] = v;
        }
    }
}

// ---------------- small kernels (PROVEN) ----------------
__global__ void sumk_kernel() {
    int idx = blockIdx.x * blockDim.x + threadIdx.x;
    if (idx < NH * S_LEN) {
        const float* p = &g_pk[(size_t)idx * NB];
        float s = 0.f;
#pragma unroll
        for (int d = 0; d < NB; ++d) s += p[d];
        g_sumk[idx] = s;
    }
}
__global__ void bias_kernel(const float* __restrict__ e0, const float* __restrict__ Wo) {
    int n = blockIdx.x * blockDim.x + threadIdx.x;
    if (n < D_DIM) {
        float s = 0.f;
        for (int j = 0; j < HB; ++j) s = fmaf(e0[j], Wo[(size_t)j * D_DIM + n], s);
        g_bias[n] = s;
    }
}

// ---------------- causal attention (fp32, PROVEN) ----------------
__global__ void __launch_bounds__(128) attn_kernel(
    const float* __restrict__ e0, const float* __restrict__ e1)
{
    const int h = blockIdx.y;
    const int qt = blockIdx.x;
    const int tid = threadIdx.x;
    const int q = qt * 128 + tid;

    __shared__ __align__(16) float sk[128 * 8];
    __shared__ __align__(16) float sv[128 * 8];
    __shared__ float ssum[128];

    float pq[8];
    {
        const float4* p = (const float4*)&g_pq[((size_t)h * S_LEN + q) * NB];
        float4 p0 = p[0], p1 = p[1];
        pq[0] = p0.x; pq[1] = p0.y; pq[2] = p0.z; pq[3] = p0.w;
        pq[4] = p1.x; pq[5] = p1.y; pq[6] = p1.z; pq[7] = p1.w;
    }
    float acc[8] = {0, 0, 0, 0, 0, 0, 0, 0};
    float l = 0.f;

    const float* kbase = &g_pk[(size_t)h * S_LEN * NB];
    const float* vbase = &g_pv[(size_t)h * S_LEN * NB];

    for (int kt = 0; kt <= qt; ++kt) {
        const float4* kp = (const float4*)(kbase + (size_t)kt * 128 * NB);
        const float4* vp = (const float4*)(vbase + (size_t)kt * 128 * NB);
        ((float4*)sk)[tid]       = kp[tid];
        ((float4*)sk)[tid + 128] = kp[tid + 128];
        ((float4*)sv)[tid]       = vp[tid];
        ((float4*)sv)[tid + 128] = vp[tid + 128];
        ssum[tid] = g_sumk[h * S_LEN + kt * 128 + tid];
        __syncthreads();

        const int kmax = (kt == qt) ? (tid + 1) : 128;
        const float4* sk4 = (const float4*)sk;
        const float4* sv4 = (const float4*)sv;
        for (int kk = 0; kk < kmax; ++kk) {
            float4 k0 = sk4[kk * 2];
            float4 k1 = sk4[kk * 2 + 1];
            float dot = -ssum[kk];
            dot = fmaf(pq[0], k0.x, dot); dot = fmaf(pq[1], k0.y, dot);
            dot = fmaf(pq[2], k0.z, dot); dot = fmaf(pq[3], k0.w, dot);
            dot = fmaf(pq[4], k1.x, dot); dot = fmaf(pq[5], k1.y, dot);
            dot = fmaf(pq[6], k1.z, dot); dot = fmaf(pq[7], k1.w, dot);
            float e = __expf(dot);
            l += e;
            float4 v0 = sv4[kk * 2];
            float4 v1 = sv4[kk * 2 + 1];
            acc[0] = fmaf(e, v0.x, acc[0]); acc[1] = fmaf(e, v0.y, acc[1]);
            acc[2] = fmaf(e, v0.z, acc[2]); acc[3] = fmaf(e, v0.w, acc[3]);
            acc[4] = fmaf(e, v1.x, acc[4]); acc[5] = fmaf(e, v1.y, acc[5]);
            acc[6] = fmaf(e, v1.z, acc[6]); acc[7] = fmaf(e, v1.w, acc[7]);
        }
        __syncthreads();
    }

    float inv = 1.0f / l;
    float o[8];
#pragma unroll
    for (int d = 0; d < 8; ++d) {
        int j = h * 8 + d;
        o[d] = acc[d] * inv * (e1[j] - e0[j]);
    }
    float4* outp = (float4*)&g_op[(size_t)q * HB + h * 8];
    outp[0] = make_float4(o[0], o[1], o[2], o[3]);
    outp[1] = make_float4(o[4], o[5], o[6], o[7]);
}

// ---------------- launch ----------------
extern "C" void kernel_launch(void* const* d_in, const int* in_sizes, int n_in,
                              void* d_out, int out_size)
{
    (void)in_sizes; (void)n_in; (void)out_size;
    const float* hs = (const float*)d_in[0];
    const float* Wq = (const float*)d_in[1];
    const float* Wk = (const float*)d_in[2];
    const float* Wv = (const float*)d_in[3];
    const float* Wo = (const float*)d_in[4];
    const float* Wg = (const float*)d_in[5];
    const float* e0 = (const float*)d_in[6];
    const float* e1 = (const float*)d_in[7];
    float* out = (float*)d_out;

    // exact scales
    init_amax<<<1, 32>>>();
    amax_kernel<<<512, 256>>>(hs, S_LEN * D_DIM, 0);
    amax_kernel<<<256, 256>>>(Wq, D_DIM * HB, 1);
    amax_kernel<<<256, 256>>>(Wk, D_DIM * HB, 1);
    amax_kernel<<<256, 256>>>(Wv, D_DIM * HB, 1);
    amax_kernel<<<512, 256>>>(Wg, D_DIM * D_DIM, 1);

    // int8 2-term packing
    dim3 tb(32, 8);
    pack_act<<<dim3(S_LEN / 32, D_DIM / 32), tb>>>(hs);
    pack_w<<<dim3(HB / 32, D_DIM / 32), tb>>>(Wq, HB, 0);
    pack_w<<<dim3(HB / 32, D_DIM / 32), tb>>>(Wk, HB, 256);
    pack_w<<<dim3(HB / 32, D_DIM / 32), tb>>>(Wv, HB, 512);
    pack_w<<<dim3(D_DIM / 32, D_DIM / 32), tb>>>(Wg, D_DIM, 768);

    bias_kernel<<<(D_DIM + 255) / 256, 256>>>(e0, Wo);

    // fused qkv+gate int8 GEMM (dp4a)
    fused_int8<<<dim3(NBIG / 128, S_LEN / 128), 256>>>(out);

    sumk_kernel<<<(NH * S_LEN + 255) / 256, 256>>>();
    attn_kernel<<<dim3(S_LEN / 128, NH), 128>>>(e0, e1);

    // final (fp32 PROVEN): out = (g_op @ Wo + bias) * sigmoid(out)
    final_gemm<<<dim3(D_DIM / 128, S_LEN / 128), 256>>>(Wo, out);
}

// round 16
// speedup vs baseline: 1.1364x; 1.1364x over previous
#include <cuda_runtime.h>
#include <cuda_fp16.h>
#include <cstdint>

#define S_LEN 2048
#define D_DIM 2048
#define NH 32
#define NB 8
#define HB 256    // NH*NB

// -------- scratch (no allocations allowed) --------
__device__ float g_pq[NH * S_LEN * NB];   // [h][s][bit], pre-scaled by 2
__device__ float g_pk[NH * S_LEN * NB];
__device__ float g_pv[NH * S_LEN * NB];
__device__ float g_sumk[NH * S_LEN];
__device__ float g_op[S_LEN * HB];        // (e1-e0)*attn_out
__device__ float g_bias[D_DIM];           // e0 @ Wo

__device__ __half g_hsT16[D_DIM * S_LEN]; // hs transposed -> [k][m], fp16
__device__ __half g_Wg16[D_DIM * D_DIM];  // Wg [k][n], fp16

__device__ __forceinline__ float fsigmoid(float x) {
    return 1.0f / (1.0f + __expf(-x));
}
__device__ __forceinline__ uint32_t smem_u32(const void* p) {
    uint32_t a;
    asm("{ .reg .u64 t; cvta.to.shared.u64 t, %1; cvt.u32.u64 %0, t; }" : "=r"(a) : "l"(p));
    return a;
}
__device__ __forceinline__ void cp16(uint32_t dst, const void* src) {
    asm volatile("cp.async.cg.shared.global [%0], [%1], 16;" :: "r"(dst), "l"(src));
}
__device__ __forceinline__ void cp_commit() {
    asm volatile("cp.async.commit_group;" ::: "memory");
}
template <int N> __device__ __forceinline__ void cp_wait() {
    asm volatile("cp.async.wait_group %0;" :: "n"(N) : "memory");
}
__device__ __forceinline__ void fma2(float2& d, float2 a, float2 b) {
    asm("fma.rn.f32x2 %0, %1, %2, %0;"
        : "+l"(reinterpret_cast<unsigned long long&>(d))
        : "l"(reinterpret_cast<unsigned long long&>(a)),
          "l"(reinterpret_cast<unsigned long long&>(b)));
}
__device__ __forceinline__ float2 dup2(float a) {
    float2 r;
    asm("mov.b64 %0, {%1, %1};"
        : "=l"(reinterpret_cast<unsigned long long&>(r)) : "f"(a));
    return r;
}

// ---------------- packing kernels ----------------
// g_hsT16[k][m] = (half)hs[m][k]
__global__ void pack_hsT16(const float* __restrict__ hs) {
    __shared__ float t[32][33];
    int m0 = blockIdx.x * 32, k0 = blockIdx.y * 32;
    int tx = threadIdx.x, ty = threadIdx.y;
#pragma unroll
    for (int i = 0; i < 32; i += 8)
        t[ty + i][tx] = hs[(size_t)(m0 + ty + i) * D_DIM + k0 + tx];
    __syncthreads();
#pragma unroll
    for (int i = 0; i < 32; i += 8)
        g_hsT16[(size_t)(k0 + ty + i) * S_LEN + m0 + tx] = __float2half(t[tx][ty + i]);
}
// g_Wg16 = (half)Wg (same layout [k][n])
__global__ void pack_Wg16(const float* __restrict__ Wg) {
    int i = blockIdx.x * blockDim.x + threadIdx.x;   // float4 index
    if (i >= D_DIM * D_DIM / 4) return;
    float4 v = ((const float4*)Wg)[i];
    __half2* d = (__half2*)g_Wg16;
    d[i * 2]     = __floats2half2_rn(v.x, v.y);
    d[i * 2 + 1] = __floats2half2_rn(v.z, v.w);
}

// ---------------- f32 GEMM core (PROVEN R12) ----------------
#define GBK 16
#define AROW 20
#define ASZ (128 * AROW)
#define BSZ (GBK * 128)
#define FUSED_SMEM ((2 * ASZ + 2 * BSZ) * 4)   // 36864 B

__device__ __forceinline__ void g_load_chunk(
    const float* __restrict__ A, const float* __restrict__ B,
    int K, int Nst, int arow0, int bcol, int k0,
    float* as, float* bs, int tid)
{
#pragma unroll
    for (int i = 0; i < 2; ++i) {
        int idx = tid + i * 256;
        int r = idx >> 2, q = idx & 3;
        cp16(smem_u32(as + r * AROW + q * 4),
             A + (size_t)(arow0 + r) * K + k0 + q * 4);
    }
#pragma unroll
    for (int i = 0; i < 2; ++i) {
        int idx = tid + i * 256;
        int kr = idx >> 5, nq = idx & 31;
        cp16(smem_u32(bs + kr * 128 + nq * 4),
             B + (size_t)(k0 + kr) * Nst + bcol + nq * 4);
    }
}
__device__ __forceinline__ void g_compute_chunk(
    const float* __restrict__ as, const float* __restrict__ bs,
    int m0, int n0, float2 (&acc)[8][4])
{
#pragma unroll
    for (int k = 0; k < GBK; ++k) {
        float a[8];
#pragma unroll
        for (int mi = 0; mi < 8; ++mi) a[mi] = as[(m0 + mi) * AROW + k];
        float4 b0 = *(const float4*)&bs[k * 128 + n0];
        float4 b1 = *(const float4*)&bs[k * 128 + n0 + 4];
        float2 b2[4] = {{b0.x, b0.y}, {b0.z, b0.w}, {b1.x, b1.y}, {b1.z, b1.w}};
#pragma unroll
        for (int mi = 0; mi < 8; ++mi) {
            float2 am = dup2(a[mi]);
#pragma unroll
            for (int n2 = 0; n2 < 4; ++n2) fma2(acc[mi][n2], am, b2[n2]);
        }
    }
}

// ---------------- fused: qkv (fp32) + gate (fp16 HFMA2) ----------------
// grid (22, 16): x<6 -> qkv (Wq/Wk/Wv, 2 col tiles each, fp32 core);
//                x>=6 -> gate col tile (fp16 core).
__global__ void __launch_bounds__(256) fused_qkvgate(
    const float* __restrict__ hs, const float* __restrict__ Wq,
    const float* __restrict__ Wk, const float* __restrict__ Wv,
    float* __restrict__ out)
{
    extern __shared__ __align__(16) char smem[];
    const int tid = threadIdx.x;
    const int xt = blockIdx.x;
    const int brow = blockIdx.y * 128;
    const int m0 = (tid >> 4) * 8, n0 = (tid & 15) * 8;

    if (xt < 6) {
        // ---------- qkv: fp32 core (PROVEN R12) ----------
        float* f = (float*)smem;
        float* As0 = f;           float* As1 = f + ASZ;
        float* Bs0 = f + 2 * ASZ; float* Bs1 = f + 2 * ASZ + BSZ;
        const int mat = xt >> 1;
        const float* Bsrc = (mat == 0) ? Wq : (mat == 1) ? Wk : Wv;
        const int bcol = (xt & 1) * 128;

        float2 acc[8][4];
#pragma unroll
        for (int mi = 0; mi < 8; ++mi)
#pragma unroll
            for (int n2 = 0; n2 < 4; ++n2) acc[mi][n2] = make_float2(0.f, 0.f);

        const int nch = D_DIM / GBK;
        g_load_chunk(hs, Bsrc, D_DIM, HB, brow, bcol, 0, As0, Bs0, tid);
        cp_commit();
        for (int c = 0; c < nch; ++c) {
            if (c + 1 < nch)
                g_load_chunk(hs, Bsrc, D_DIM, HB, brow, bcol, (c + 1) * GBK,
                             ((c + 1) & 1) ? As1 : As0, ((c + 1) & 1) ? Bs1 : Bs0, tid);
            cp_commit();
            cp_wait<1>();
            __syncthreads();
            g_compute_chunk((c & 1) ? As1 : As0, (c & 1) ? Bs1 : Bs0, m0, n0, acc);
            __syncthreads();
        }

        float* dst = (mat == 0) ? g_pq : (mat == 1) ? g_pk : g_pv;
        const float scl = (mat == 0) ? 2.0f : 1.0f;
#pragma unroll
        for (int mi = 0; mi < 8; ++mi) {
            int s = brow + m0 + mi;
#pragma unroll
            for (int n2 = 0; n2 < 4; ++n2) {
                int c = bcol + n0 + 2 * n2;
                int h = c >> 3, d = c & 7;
                float2 v = acc[mi][n2];
                v.x = scl * fsigmoid(v.x);
                v.y = scl * fsigmoid(v.y);
                *(float2*)&dst[((size_t)h * S_LEN + s) * NB + d] = v;
            }
        }
    } else {
        // ---------- gate: fp16 HFMA2 core, fp32 fold every 8 k ----------
        __half* hbuf = (__half*)smem;
        __half* ah[2] = {hbuf, hbuf + 2048};          // 16k x 128m halves per stage
        __half* bh[2] = {hbuf + 4096, hbuf + 6144};   // 16k x 128n
        const int bcol = (xt - 6) * 128;

        __half2 hacc[8][4];
        float2 facc[8][4];
#pragma unroll
        for (int mi = 0; mi < 8; ++mi)
#pragma unroll
            for (int nj = 0; nj < 4; ++nj) {
                hacc[mi][nj] = __float2half2_rn(0.f);
                facc[mi][nj] = make_float2(0.f, 0.f);
            }

        const int kr = tid >> 4, q8 = (tid & 15) * 8;
        const int nch = D_DIM / 16;

        auto load16 = [&](int c) {
            const int k0 = c * 16;
            const int s = c & 1;
            cp16(smem_u32(ah[s] + kr * 128 + q8),
                 g_hsT16 + (size_t)(k0 + kr) * S_LEN + brow + q8);
            cp16(smem_u32(bh[s] + kr * 128 + q8),
                 g_Wg16 + (size_t)(k0 + kr) * D_DIM + bcol + q8);
        };

        load16(0);
        cp_commit();
        for (int c = 0; c < nch; ++c) {
            if (c + 1 < nch) load16(c + 1);
            cp_commit();
            cp_wait<1>();
            __syncthreads();
            const __half* as = ah[c & 1];
            const __half* bs = bh[c & 1];
#pragma unroll
            for (int k = 0; k < 16; ++k) {
                const __half2* ap = (const __half2*)(as + k * 128 + m0);
                const __half2* bp = (const __half2*)(bs + k * 128 + n0);
                __half2 p0 = ap[0], p1 = ap[1], p2 = ap[2], p3 = ap[3];
                __half2 b2[4] = {bp[0], bp[1], bp[2], bp[3]};
                __half2 ad[8];
                ad[0] = __lows2half2(p0, p0);  ad[1] = __highs2half2(p0, p0);
                ad[2] = __lows2half2(p1, p1);  ad[3] = __highs2half2(p1, p1);
                ad[4] = __lows2half2(p2, p2);  ad[5] = __highs2half2(p2, p2);
                ad[6] = __lows2half2(p3, p3);  ad[7] = __highs2half2(p3, p3);
#pragma unroll
                for (int mi = 0; mi < 8; ++mi)
#pragma unroll
                    for (int nj = 0; nj < 4; ++nj)
                        hacc[mi][nj] = __hfma2(ad[mi], b2[nj], hacc[mi][nj]);
                if ((k & 7) == 7) {   // fold to fp32 every 8 k
#pragma unroll
                    for (int mi = 0; mi < 8; ++mi)
#pragma unroll
                        for (int nj = 0; nj < 4; ++nj) {
                            float2 fv = __half22float2(hacc[mi][nj]);
                            facc[mi][nj].x += fv.x;
                            facc[mi][nj].y += fv.y;
                            hacc[mi][nj] = __float2half2_rn(0.f);
                        }
                }
            }
            __syncthreads();
        }

#pragma unroll
        for (int mi = 0; mi < 8; ++mi) {
            int r = brow + m0 + mi;
            size_t base = (size_t)r * D_DIM + bcol + n0;
            *(float4*)&out[base] =
                make_float4(facc[mi][0].x, facc[mi][0].y, facc[mi][1].x, facc[mi][1].y);
            *(float4*)&out[base + 4] =
                make_float4(facc[mi][2].x, facc[mi][2].y, facc[mi][3].x, facc[mi][3].y);
        }
    }
}

// ---------------- final GEMM (R12, PROVEN) ----------------
__global__ void __launch_bounds__(256) final_gemm(
    const float* __restrict__ Wo, float* __restrict__ out)
{
    __shared__ __align__(16) float As[2][ASZ];
    __shared__ __align__(16) float Bs[2][BSZ];
    const int tid = threadIdx.x;
    const int brow = blockIdx.y * 128;
    const int bcol = blockIdx.x * 128;

    float2 acc[8][4];
#pragma unroll
    for (int mi = 0; mi < 8; ++mi)
#pragma unroll
        for (int n2 = 0; n2 < 4; ++n2) acc[mi][n2] = make_float2(0.f, 0.f);

    const int m0 = (tid >> 4) * 8, n0 = (tid & 15) * 8;
    const int nch = HB / GBK;

    g_load_chunk(g_op, Wo, HB, D_DIM, brow, bcol, 0, As[0], Bs[0], tid);
    cp_commit();
    for (int c = 0; c < nch; ++c) {
        if (c + 1 < nch)
            g_load_chunk(g_op, Wo, HB, D_DIM, brow, bcol, (c + 1) * GBK,
                         As[(c + 1) & 1], Bs[(c + 1) & 1], tid);
        cp_commit();
        cp_wait<1>();
        __syncthreads();
        g_compute_chunk(As[c & 1], Bs[c & 1], m0, n0, acc);
        __syncthreads();
    }

#pragma unroll
    for (int mi = 0; mi < 8; ++mi) {
        int r = brow + m0 + mi;
        int c0 = bcol + n0;
        size_t base = (size_t)r * D_DIM + c0;
#pragma unroll
        for (int n2 = 0; n2 < 4; ++n2) {
            float2 b = *(float2*)&g_bias[c0 + 2 * n2];
            float2 g = *(float2*)&out[base + 2 * n2];
            float2 v;
            v.x = (acc[mi][n2].x + b.x) * fsigmoid(g.x);
            v.y = (acc[mi][n2].y + b.y) * fsigmoid(g.y);
            *(float2*)&out[base + 2 * n2] = v;
        }
    }
}

// ---------------- small kernels (PROVEN) ----------------
__global__ void sumk_kernel() {
    int idx = blockIdx.x * blockDim.x + threadIdx.x;
    if (idx < NH * S_LEN) {
        const float* p = &g_pk[(size_t)idx * NB];
        float s = 0.f;
#pragma unroll
        for (int d = 0; d < NB; ++d) s += p[d];
        g_sumk[idx] = s;
    }
}
__global__ void bias_kernel(const float* __restrict__ e0, const float* __restrict__ Wo) {
    int n = blockIdx.x * blockDim.x + threadIdx.x;
    if (n < D_DIM) {
        float s = 0.f;
        for (int j = 0; j < HB; ++j) s = fmaf(e0[j], Wo[(size_t)j * D_DIM + n], s);
        g_bias[n] = s;
    }
}

// ---------------- causal attention (fp32, PROVEN) ----------------
__global__ void __launch_bounds__(128) attn_kernel(
    const float* __restrict__ e0, const float* __restrict__ e1)
{
    const int h = blockIdx.y;
    const int qt = blockIdx.x;
    const int tid = threadIdx.x;
    const int q = qt * 128 + tid;

    __shared__ __align__(16) float sk[128 * 8];
    __shared__ __align__(16) float sv[128 * 8];
    __shared__ float ssum[128];

    float pq[8];
    {
        const float4* p = (const float4*)&g_pq[((size_t)h * S_LEN + q) * NB];
        float4 p0 = p[0], p1 = p[1];
        pq[0] = p0.x; pq[1] = p0.y; pq[2] = p0.z; pq[3] = p0.w;
        pq[4] = p1.x; pq[5] = p1.y; pq[6] = p1.z; pq[7] = p1.w;
    }
    float acc[8] = {0, 0, 0, 0, 0, 0, 0, 0};
    float l = 0.f;

    const float* kbase = &g_pk[(size_t)h * S_LEN * NB];
    const float* vbase = &g_pv[(size_t)h * S_LEN * NB];

    for (int kt = 0; kt <= qt; ++kt) {
        const float4* kp = (const float4*)(kbase + (size_t)kt * 128 * NB);
        const float4* vp = (const float4*)(vbase + (size_t)kt * 128 * NB);
        ((float4*)sk)[tid]       = kp[tid];
        ((float4*)sk)[tid + 128] = kp[tid + 128];
        ((float4*)sv)[tid]       = vp[tid];
        ((float4*)sv)[tid + 128] = vp[tid + 128];
        ssum[tid] = g_sumk[h * S_LEN + kt * 128 + tid];
        __syncthreads();

        const int kmax = (kt == qt) ? (tid + 1) : 128;
        const float4* sk4 = (const float4*)sk;
        const float4* sv4 = (const float4*)sv;
        for (int kk = 0; kk < kmax; ++kk) {
            float4 k0 = sk4[kk * 2];
            float4 k1 = sk4[kk * 2 + 1];
            float dot = -ssum[kk];
            dot = fmaf(pq[0], k0.x, dot); dot = fmaf(pq[1], k0.y, dot);
            dot = fmaf(pq[2], k0.z, dot); dot = fmaf(pq[3], k0.w, dot);
            dot = fmaf(pq[4], k1.x, dot); dot = fmaf(pq[5], k1.y, dot);
            dot = fmaf(pq[6], k1.z, dot); dot = fmaf(pq[7], k1.w, dot);
            float e = __expf(dot);
            l += e;
            float4 v0 = sv4[kk * 2];
            float4 v1 = sv4[kk * 2 + 1];
            acc[0] = fmaf(e, v0.x, acc[0]); acc[1] = fmaf(e, v0.y, acc[1]);
            acc[2] = fmaf(e, v0.z, acc[2]); acc[3] = fmaf(e, v0.w, acc[3]);
            acc[4] = fmaf(e, v1.x, acc[4]); acc[5] = fmaf(e, v1.y, acc[5]);
            acc[6] = fmaf(e, v1.z, acc[6]); acc[7] = fmaf(e, v1.w, acc[7]);
        }
        __syncthreads();
    }

    float inv = 1.0f / l;
    float o[8];
#pragma unroll
    for (int d = 0; d < 8; ++d) {
        int j = h * 8 + d;
        o[d] = acc[d] * inv * (e1[j] - e0[j]);
    }
    float4* outp = (float4*)&g_op[(size_t)q * HB + h * 8];
    outp[0] = make_float4(o[0], o[1], o[2], o[3]);
    outp[1] = make_float4(o[4], o[5], o[6], o[7]);
}

// ---------------- launch ----------------
extern "C" void kernel_launch(void* const* d_in, const int* in_sizes, int n_in,
                              void* d_out, int out_size)
{
    (void)in_sizes; (void)n_in; (void)out_size;
    const float* hs = (const float*)d_in[0];
    const float* Wq = (const float*)d_in[1];
    const float* Wk = (const float*)d_in[2];
    const float* Wv = (const float*)d_in[3];
    const float* Wo = (const float*)d_in[4];
    const float* Wg = (const float*)d_in[5];
    const float* e0 = (const float*)d_in[6];
    const float* e1 = (const float*)d_in[7];
    float* out = (float*)d_out;

    // fp16 packs for the gate path
    dim3 tb(32, 8);
    pack_hsT16<<<dim3(S_LEN / 32, D_DIM / 32), tb>>>(hs);
    pack_Wg16<<<(D_DIM * D_DIM / 4 + 255) / 256, 256>>>(Wg);
    bias_kernel<<<(D_DIM + 255) / 256, 256>>>(e0, Wo);

    // fused qkv (fp32) + gate (fp16 HFMA2)
    fused_qkvgate<<<dim3(22, S_LEN / 128), 256, FUSED_SMEM>>>(hs, Wq, Wk, Wv, out);

    sumk_kernel<<<(NH * S_LEN + 255) / 256, 256>>>();
    attn_kernel<<<dim3(S_LEN / 128, NH), 128>>>(e0, e1);

    // final (fp32 PROVEN): out = (g_op @ Wo + bias) * sigmoid(out)
    final_gemm<<<dim3(D_DIM / 128, S_LEN / 128), 256>>>(Wo, out);
}

// round 17
// speedup vs baseline: 1.1542x; 1.0157x over previous
#include <cuda_runtime.h>
#include <cuda_fp16.h>
#include <cstdint>

#define S_LEN 2048
#define D_DIM 2048
#define NH 32
#define NB 8
#define HB 256    // NH*NB

// -------- scratch (no allocations allowed) --------
__device__ float g_pq[NH * S_LEN * NB];   // [h][s][bit], pre-scaled by 2
__device__ float g_pk[NH * S_LEN * NB];
__device__ float g_pv[NH * S_LEN * NB];
__device__ float g_sumk[NH * S_LEN];
__device__ float g_op[S_LEN * HB];        // (e1-e0)*attn_out
__device__ float g_bias[D_DIM];           // e0 @ Wo

__device__ __half2 g_hsT16dup[D_DIM * S_LEN]; // [k][m] = half2(hs[m][k], hs[m][k])
__device__ __half  g_Wg16[D_DIM * D_DIM];     // Wg [k][n], fp16

__device__ __forceinline__ float fsigmoid(float x) {
    return 1.0f / (1.0f + __expf(-x));
}
__device__ __forceinline__ uint32_t smem_u32(const void* p) {
    uint32_t a;
    asm("{ .reg .u64 t; cvta.to.shared.u64 t, %1; cvt.u32.u64 %0, t; }" : "=r"(a) : "l"(p));
    return a;
}
__device__ __forceinline__ void cp16(uint32_t dst, const void* src) {
    asm volatile("cp.async.cg.shared.global [%0], [%1], 16;" :: "r"(dst), "l"(src));
}
__device__ __forceinline__ void cp_commit() {
    asm volatile("cp.async.commit_group;" ::: "memory");
}
template <int N> __device__ __forceinline__ void cp_wait() {
    asm volatile("cp.async.wait_group %0;" :: "n"(N) : "memory");
}
__device__ __forceinline__ void fma2(float2& d, float2 a, float2 b) {
    asm("fma.rn.f32x2 %0, %1, %2, %0;"
        : "+l"(reinterpret_cast<unsigned long long&>(d))
        : "l"(reinterpret_cast<unsigned long long&>(a)),
          "l"(reinterpret_cast<unsigned long long&>(b)));
}
__device__ __forceinline__ float2 dup2(float a) {
    float2 r;
    asm("mov.b64 %0, {%1, %1};"
        : "=l"(reinterpret_cast<unsigned long long&>(r)) : "f"(a));
    return r;
}

// ---------------- packing kernels ----------------
// g_hsT16dup[k][m] = half2(hs[m][k], hs[m][k])
__global__ void pack_hsT16dup(const float* __restrict__ hs) {
    __shared__ float t[32][33];
    int m0 = blockIdx.x * 32, k0 = blockIdx.y * 32;
    int tx = threadIdx.x, ty = threadIdx.y;
#pragma unroll
    for (int i = 0; i < 32; i += 8)
        t[ty + i][tx] = hs[(size_t)(m0 + ty + i) * D_DIM + k0 + tx];
    __syncthreads();
#pragma unroll
    for (int i = 0; i < 32; i += 8) {
        __half h = __float2half(t[tx][ty + i]);
        g_hsT16dup[(size_t)(k0 + ty + i) * S_LEN + m0 + tx] = __half2(h, h);
    }
}
// g_Wg16 = (half)Wg (layout [k][n])
__global__ void pack_Wg16(const float* __restrict__ Wg) {
    int i = blockIdx.x * blockDim.x + threadIdx.x;
    if (i >= D_DIM * D_DIM / 4) return;
    float4 v = ((const float4*)Wg)[i];
    __half2* d = (__half2*)g_Wg16;
    d[i * 2]     = __floats2half2_rn(v.x, v.y);
    d[i * 2 + 1] = __floats2half2_rn(v.z, v.w);
}

// ---------------- f32 GEMM core (PROVEN R12) ----------------
#define GBK 16
#define AROW 20
#define ASZ (128 * AROW)
#define BSZ (GBK * 128)

__device__ __forceinline__ void g_load_chunk(
    const float* __restrict__ A, const float* __restrict__ B,
    int K, int Nst, int arow0, int bcol, int k0,
    float* as, float* bs, int tid)
{
#pragma unroll
    for (int i = 0; i < 2; ++i) {
        int idx = tid + i * 256;
        int r = idx >> 2, q = idx & 3;
        cp16(smem_u32(as + r * AROW + q * 4),
             A + (size_t)(arow0 + r) * K + k0 + q * 4);
    }
#pragma unroll
    for (int i = 0; i < 2; ++i) {
        int idx = tid + i * 256;
        int kr = idx >> 5, nq = idx & 31;
        cp16(smem_u32(bs + kr * 128 + nq * 4),
             B + (size_t)(k0 + kr) * Nst + bcol + nq * 4);
    }
}
__device__ __forceinline__ void g_compute_chunk(
    const float* __restrict__ as, const float* __restrict__ bs,
    int m0, int n0, float2 (&acc)[8][4])
{
#pragma unroll
    for (int k = 0; k < GBK; ++k) {
        float a[8];
#pragma unroll
        for (int mi = 0; mi < 8; ++mi) a[mi] = as[(m0 + mi) * AROW + k];
        float4 b0 = *(const float4*)&bs[k * 128 + n0];
        float4 b1 = *(const float4*)&bs[k * 128 + n0 + 4];
        float2 b2[4] = {{b0.x, b0.y}, {b0.z, b0.w}, {b1.x, b1.y}, {b1.z, b1.w}};
#pragma unroll
        for (int mi = 0; mi < 8; ++mi) {
            float2 am = dup2(a[mi]);
#pragma unroll
            for (int n2 = 0; n2 < 4; ++n2) fma2(acc[mi][n2], am, b2[n2]);
        }
    }
}

// ---------------- qkv GEMM (fp32, PROVEN) ----------------
__global__ void __launch_bounds__(256) qkv_gemm(
    const float* __restrict__ hs, const float* __restrict__ Wq,
    const float* __restrict__ Wk, const float* __restrict__ Wv)
{
    __shared__ __align__(16) float As[2][ASZ];
    __shared__ __align__(16) float Bs[2][BSZ];

    const int tid = threadIdx.x;
    const int mat = blockIdx.x >> 1;
    const float* Bsrc = (mat == 0) ? Wq : (mat == 1) ? Wk : Wv;
    const int bcol = (blockIdx.x & 1) * 128;
    const int brow = blockIdx.y * 128;

    float2 acc[8][4];
#pragma unroll
    for (int mi = 0; mi < 8; ++mi)
#pragma unroll
        for (int n2 = 0; n2 < 4; ++n2) acc[mi][n2] = make_float2(0.f, 0.f);

    const int m0 = (tid >> 4) * 8, n0 = (tid & 15) * 8;
    const int nch = D_DIM / GBK;

    g_load_chunk(hs, Bsrc, D_DIM, HB, brow, bcol, 0, As[0], Bs[0], tid);
    cp_commit();
    for (int c = 0; c < nch; ++c) {
        if (c + 1 < nch)
            g_load_chunk(hs, Bsrc, D_DIM, HB, brow, bcol, (c + 1) * GBK,
                         As[(c + 1) & 1], Bs[(c + 1) & 1], tid);
        cp_commit();
        cp_wait<1>();
        __syncthreads();
        g_compute_chunk(As[c & 1], Bs[c & 1], m0, n0, acc);
        __syncthreads();
    }

    float* dst = (mat == 0) ? g_pq : (mat == 1) ? g_pk : g_pv;
    const float scl = (mat == 0) ? 2.0f : 1.0f;
#pragma unroll
    for (int mi = 0; mi < 8; ++mi) {
        int s = brow + m0 + mi;
#pragma unroll
        for (int n2 = 0; n2 < 4; ++n2) {
            int c = bcol + n0 + 2 * n2;
            int h = c >> 3, d = c & 7;
            float2 v = acc[mi][n2];
            v.x = scl * fsigmoid(v.x);
            v.y = scl * fsigmoid(v.y);
            *(float2*)&dst[((size_t)h * S_LEN + s) * NB + d] = v;
        }
    }
}

// ---------------- gate GEMM (fp16 HFMA2, issue-lean) ----------------
// A: g_hsT16dup [k][m] half2-dup; B: g_Wg16 [k][n] half.
// CTA 128x128, 16 k per chunk. smem/stage: A 8KB (dup) + B 4KB -> 24KB total.
#define HA_H2 (16 * 128)            // half2 per A stage
#define HB_H  (16 * 128)            // half per B stage
__global__ void __launch_bounds__(256, 2) gate_fp16(float* __restrict__ out) {
    __shared__ __align__(16) __half2 Ah[2][HA_H2];
    __shared__ __align__(16) __half  Bh[2][HB_H];

    const int tid = threadIdx.x;
    const int bcol = blockIdx.x * 128;
    const int brow = blockIdx.y * 128;
    const int m0 = (tid >> 4) * 8, n0 = (tid & 15) * 8;

    __half2 hacc[8][4];
    float2 facc[8][4];
#pragma unroll
    for (int mi = 0; mi < 8; ++mi)
#pragma unroll
        for (int nj = 0; nj < 4; ++nj) {
            hacc[mi][nj] = __float2half2_rn(0.f);
            facc[mi][nj] = make_float2(0.f, 0.f);
        }

    // loaders: A 8KB = 512 x 16B (2/thread); B 4KB = 256 x 16B (1/thread)
    const int ar = tid >> 5, ac = tid & 31;        // A: rows ar, ar+8; 16B chunk ac
    const int br = tid >> 4, bc = tid & 15;        // B: row br; 16B chunk bc

    auto load16 = [&](int c) {
        const int k0 = c * 16;
        const int s = c & 1;
        cp16(smem_u32((char*)Ah[s] + ar * 512 + ac * 16),
             g_hsT16dup + (size_t)(k0 + ar) * S_LEN + brow + ac * 4);
        cp16(smem_u32((char*)Ah[s] + (ar + 8) * 512 + ac * 16),
             g_hsT16dup + (size_t)(k0 + ar + 8) * S_LEN + brow + ac * 4);
        cp16(smem_u32((char*)Bh[s] + br * 256 + bc * 16),
             g_Wg16 + (size_t)(k0 + br) * D_DIM + bcol + bc * 8);
    };

    const int nch = D_DIM / 16;
    load16(0);
    cp_commit();
    for (int c = 0; c < nch; ++c) {
        if (c + 1 < nch) load16(c + 1);
        cp_commit();
        cp_wait<1>();
        __syncthreads();
        const __half2* as = Ah[c & 1];
        const __half* bs = Bh[c & 1];
#pragma unroll
        for (int k = 0; k < 16; ++k) {
            // A: 8 dup half2 = 32B = 2 LDS.128
            float4 av0 = *(const float4*)&as[k * 128 + m0];
            float4 av1 = *(const float4*)&as[k * 128 + m0 + 4];
            const __half2* ad0 = (const __half2*)&av0;
            const __half2* ad1 = (const __half2*)&av1;
            // B: 4 half2 = 16B = 1 LDS.128
            float4 bv = *(const float4*)&bs[k * 128 + n0];
            const __half2* b2 = (const __half2*)&bv;
#pragma unroll
            for (int mi = 0; mi < 4; ++mi)
#pragma unroll
                for (int nj = 0; nj < 4; ++nj)
                    hacc[mi][nj] = __hfma2(ad0[mi], b2[nj], hacc[mi][nj]);
#pragma unroll
            for (int mi = 0; mi < 4; ++mi)
#pragma unroll
                for (int nj = 0; nj < 4; ++nj)
                    hacc[mi + 4][nj] = __hfma2(ad1[mi], b2[nj], hacc[mi + 4][nj]);
            if ((k & 7) == 7) {   // fold to fp32 every 8 k
#pragma unroll
                for (int mi = 0; mi < 8; ++mi)
#pragma unroll
                    for (int nj = 0; nj < 4; ++nj) {
                        float2 fv = __half22float2(hacc[mi][nj]);
                        facc[mi][nj].x += fv.x;
                        facc[mi][nj].y += fv.y;
                        hacc[mi][nj] = __float2half2_rn(0.f);
                    }
            }
        }
        __syncthreads();
    }

#pragma unroll
    for (int mi = 0; mi < 8; ++mi) {
        int r = brow + m0 + mi;
        size_t base = (size_t)r * D_DIM + bcol + n0;
        *(float4*)&out[base] =
            make_float4(facc[mi][0].x, facc[mi][0].y, facc[mi][1].x, facc[mi][1].y);
        *(float4*)&out[base + 4] =
            make_float4(facc[mi][2].x, facc[mi][2].y, facc[mi][3].x, facc[mi][3].y);
    }
}

// ---------------- final GEMM (fp32, PROVEN) ----------------
__global__ void __launch_bounds__(256) final_gemm(
    const float* __restrict__ Wo, float* __restrict__ out)
{
    __shared__ __align__(16) float As[2][ASZ];
    __shared__ __align__(16) float Bs[2][BSZ];
    const int tid = threadIdx.x;
    const int brow = blockIdx.y * 128;
    const int bcol = blockIdx.x * 128;

    float2 acc[8][4];
#pragma unroll
    for (int mi = 0; mi < 8; ++mi)
#pragma unroll
        for (int n2 = 0; n2 < 4; ++n2) acc[mi][n2] = make_float2(0.f, 0.f);

    const int m0 = (tid >> 4) * 8, n0 = (tid & 15) * 8;
    const int nch = HB / GBK;

    g_load_chunk(g_op, Wo, HB, D_DIM, brow, bcol, 0, As[0], Bs[0], tid);
    cp_commit();
    for (int c = 0; c < nch; ++c) {
        if (c + 1 < nch)
            g_load_chunk(g_op, Wo, HB, D_DIM, brow, bcol, (c + 1) * GBK,
                         As[(c + 1) & 1], Bs[(c + 1) & 1], tid);
        cp_commit();
        cp_wait<1>();
        __syncthreads();
        g_compute_chunk(As[c & 1], Bs[c & 1], m0, n0, acc);
        __syncthreads();
    }

#pragma unroll
    for (int mi = 0; mi < 8; ++mi) {
        int r = brow + m0 + mi;
        int c0 = bcol + n0;
        size_t base = (size_t)r * D_DIM + c0;
#pragma unroll
        for (int n2 = 0; n2 < 4; ++n2) {
            float2 b = *(float2*)&g_bias[c0 + 2 * n2];
            float2 g = *(float2*)&out[base + 2 * n2];
            float2 v;
            v.x = (acc[mi][n2].x + b.x) * fsigmoid(g.x);
            v.y = (acc[mi][n2].y + b.y) * fsigmoid(g.y);
            *(float2*)&out[base + 2 * n2] = v;
        }
    }
}

// ---------------- small kernels (PROVEN) ----------------
__global__ void sumk_kernel() {
    int idx = blockIdx.x * blockDim.x + threadIdx.x;
    if (idx < NH * S_LEN) {
        const float* p = &g_pk[(size_t)idx * NB];
        float s = 0.f;
#pragma unroll
        for (int d = 0; d < NB; ++d) s += p[d];
        g_sumk[idx] = s;
    }
}
__global__ void bias_kernel(const float* __restrict__ e0, const float* __restrict__ Wo) {
    int n = blockIdx.x * blockDim.x + threadIdx.x;
    if (n < D_DIM) {
        float s = 0.f;
        for (int j = 0; j < HB; ++j) s = fmaf(e0[j], Wo[(size_t)j * D_DIM + n], s);
        g_bias[n] = s;
    }
}

// ---------------- causal attention (fp32, PROVEN) ----------------
__global__ void __launch_bounds__(128) attn_kernel(
    const float* __restrict__ e0, const float* __restrict__ e1)
{
    const int h = blockIdx.y;
    const int qt = blockIdx.x;
    const int tid = threadIdx.x;
    const int q = qt * 128 + tid;

    __shared__ __align__(16) float sk[128 * 8];
    __shared__ __align__(16) float sv[128 * 8];
    __shared__ float ssum[128];

    float pq[8];
    {
        const float4* p = (const float4*)&g_pq[((size_t)h * S_LEN + q) * NB];
        float4 p0 = p[0], p1 = p[1];
        pq[0] = p0.x; pq[1] = p0.y; pq[2] = p0.z; pq[3] = p0.w;
        pq[4] = p1.x; pq[5] = p1.y; pq[6] = p1.z; pq[7] = p1.w;
    }
    float acc[8] = {0, 0, 0, 0, 0, 0, 0, 0};
    float l = 0.f;

    const float* kbase = &g_pk[(size_t)h * S_LEN * NB];
    const float* vbase = &g_pv[(size_t)h * S_LEN * NB];

    for (int kt = 0; kt <= qt; ++kt) {
        const float4* kp = (const float4*)(kbase + (size_t)kt * 128 * NB);
        const float4* vp = (const float4*)(vbase + (size_t)kt * 128 * NB);
        ((float4*)sk)[tid]       = kp[tid];
        ((float4*)sk)[tid + 128] = kp[tid + 128];
        ((float4*)sv)[tid]       = vp[tid];
        ((float4*)sv)[tid + 128] = vp[tid + 128];
        ssum[tid] = g_sumk[h * S_LEN + kt * 128 + tid];
        __syncthreads();

        const int kmax = (kt == qt) ? (tid + 1) : 128;
        const float4* sk4 = (const float4*)sk;
        const float4* sv4 = (const float4*)sv;
        for (int kk = 0; kk < kmax; ++kk) {
            float4 k0 = sk4[kk * 2];
            float4 k1 = sk4[kk * 2 + 1];
            float dot = -ssum[kk];
            dot = fmaf(pq[0], k0.x, dot); dot = fmaf(pq[1], k0.y, dot);
            dot = fmaf(pq[2], k0.z, dot); dot = fmaf(pq[3], k0.w, dot);
            dot = fmaf(pq[4], k1.x, dot); dot = fmaf(pq[5], k1.y, dot);
            dot = fmaf(pq[6], k1.z, dot); dot = fmaf(pq[7], k1.w, dot);
            float e = __expf(dot);
            l += e;
            float4 v0 = sv4[kk * 2];
            float4 v1 = sv4[kk * 2 + 1];
            acc[0] = fmaf(e, v0.x, acc[0]); acc[1] = fmaf(e, v0.y, acc[1]);
            acc[2] = fmaf(e, v0.z, acc[2]); acc[3] = fmaf(e, v0.w, acc[3]);
            acc[4] = fmaf(e, v1.x, acc[4]); acc[5] = fmaf(e, v1.y, acc[5]);
            acc[6] = fmaf(e, v1.z, acc[6]); acc[7] = fmaf(e, v1.w, acc[7]);
        }
        __syncthreads();
    }

    float inv = 1.0f / l;
    float o[8];
#pragma unroll
    for (int d = 0; d < 8; ++d) {
        int j = h * 8 + d;
        o[d] = acc[d] * inv * (e1[j] - e0[j]);
    }
    float4* outp = (float4*)&g_op[(size_t)q * HB + h * 8];
    outp[0] = make_float4(o[0], o[1], o[2], o[3]);
    outp[1] = make_float4(o[4], o[5], o[6], o[7]);
}

// ---------------- launch ----------------
extern "C" void kernel_launch(void* const* d_in, const int* in_sizes, int n_in,
                              void* d_out, int out_size)
{
    (void)in_sizes; (void)n_in; (void)out_size;
    const float* hs = (const float*)d_in[0];
    const float* Wq = (const float*)d_in[1];
    const float* Wk = (const float*)d_in[2];
    const float* Wv = (const float*)d_in[3];
    const float* Wo = (const float*)d_in[4];
    const float* Wg = (const float*)d_in[5];
    const float* e0 = (const float*)d_in[6];
    const float* e1 = (const float*)d_in[7];
    float* out = (float*)d_out;

    dim3 tb(32, 8);
    pack_hsT16dup<<<dim3(S_LEN / 32, D_DIM / 32), tb>>>(hs);
    pack_Wg16<<<(D_DIM * D_DIM / 4 + 255) / 256, 256>>>(Wg);
    bias_kernel<<<(D_DIM + 255) / 256, 256>>>(e0, Wo);

    // qkv projections (fp32, proven)
    qkv_gemm<<<dim3(6, S_LEN / 128), 256>>>(hs, Wq, Wk, Wv);
    sumk_kernel<<<(NH * S_LEN + 255) / 256, 256>>>();

    // gate preact (fp16 HFMA2, issue-lean) -> out
    gate_fp16<<<dim3(D_DIM / 128, S_LEN / 128), 256>>>(out);

    attn_kernel<<<dim3(S_LEN / 128, NH), 128>>>(e0, e1);

    // final (fp32, proven): out = (g_op @ Wo + bias) * sigmoid(out)
    final_gemm<<<dim3(D_DIM / 128, S_LEN / 128), 256>>>(Wo, out);
}